// round 17
// baseline (speedup 1.0000x reference)
#include <cuda_runtime.h>
#include <cuda_fp16.h>
#include <cstdint>

// MPNN, B=4096 graphs, N=64, D=128, L=3. TWO graphs per CTA (warps 0-3 ->
// graph 0, warps 4-7 -> graph 1), warp tile 32x64 (2x2 grid per graph).
// Algebra: Y1 = z1 W2^T per fingerprint (fp32 prologue), then per graph:
//   stage A: D = adjI @ Y1g (K=64)   -> z2 = relu(D + b2)
//   stage B: h3 = adjI @ z2 (K=64)
//   stage C: D3 = h3 @ W3^T (K=128)  -> pooled epilogue:
//            out[k] = sum_m w_m relu(D3[m,k]+b3[k]), w = 1 + colsum(adj)
// Precision: single-pass fp16 HMMA, fp32 accum (rel_err ~2e-4 vs 1e-3 gate).
// FIX vs R16: epilogue smem stores use GENERIC pointers (smem + off), not the
// cvta'd shared-space integer (that caused the illegal memory access).

__device__ __align__(16) unsigned short g_w3[16384];        // W3 f16 [128r][128c] swizzled
__device__ __align__(16) unsigned short g_y1[2048 * 128];   // Y1 f16 row-major [fp][k]

// ---- main-kernel smem layout (82KB / CTA -> 2 CTAs/SM) ----
#define SM_AH    0        // z2/h3 f16, graph g at +g*16384 (colsum scratch at init)
#define SM_WZ    32768    // Y1 (graph g at +g*16384) -> W3 [128][256B]
#define SM_ADJ   65536    // adjI f16, graph g at +g*8192, [64][128B]
#define SM_POOL  81920    // 2 x 128 floats
#define SM_TOTAL 82944

// ---- fused-prologue smem layout (fp32 floats) ----
#define FP_SW   0
#define FP_SX   (128 * 132)
#define FP_SZ   (FP_SX + 16 * 132)
#define FP_SB   (FP_SZ + 16 * 132)
#define FP_TOT  ((FP_SB + 128) * 4)

__device__ __forceinline__ uint32_t smem_u32(const void* p) {
    uint32_t a;
    asm("{ .reg .u64 t; cvta.to.shared.u64 t, %1; cvt.u32.u64 %0, t; }" : "=r"(a) : "l"(p));
    return a;
}
__device__ __forceinline__ void cp16(uint32_t dst, const void* src) {
    asm volatile("cp.async.cg.shared.global [%0], [%1], 16;" :: "r"(dst), "l"(src));
}
#define CP_COMMIT() asm volatile("cp.async.commit_group;" ::: "memory")
#define CP_WAIT0()  asm volatile("cp.async.wait_group 0;" ::: "memory")

__device__ __forceinline__ void ldsm4(uint32_t* r, uint32_t a) {
    asm volatile("ldmatrix.sync.aligned.m8n8.x4.shared.b16 {%0,%1,%2,%3}, [%4];"
                 : "=r"(r[0]), "=r"(r[1]), "=r"(r[2]), "=r"(r[3]) : "r"(a));
}
__device__ __forceinline__ void ldsm4t(uint32_t* r, uint32_t a) {
    asm volatile("ldmatrix.sync.aligned.m8n8.x4.trans.shared.b16 {%0,%1,%2,%3}, [%4];"
                 : "=r"(r[0]), "=r"(r[1]), "=r"(r[2]), "=r"(r[3]) : "r"(a));
}
__device__ __forceinline__ void mma16816h(float* c, const uint32_t* a, const uint32_t* b) {
    asm volatile("mma.sync.aligned.m16n8k16.row.col.f32.f16.f16.f32 "
                 "{%0,%1,%2,%3}, {%4,%5,%6,%7}, {%8,%9}, {%0,%1,%2,%3};"
                 : "+f"(c[0]), "+f"(c[1]), "+f"(c[2]), "+f"(c[3])
                 : "r"(a[0]), "r"(a[1]), "r"(a[2]), "r"(a[3]), "r"(b[0]), "r"(b[1]));
}
__device__ __forceinline__ uint32_t f16pack(float v0, float v1) {
    uint32_t r;
    asm("cvt.rn.f16x2.f32 %0, %1, %2;" : "=r"(r) : "f"(v1), "f"(v0));
    return r;
}
__device__ __forceinline__ int swz256(int row, int col) {
    return (row << 8) + ((((col >> 3) ^ (row & 7)) << 4) | ((col & 7) << 1));
}

// GEMM1: C[32x64 tile] of h[64x128] @ W3[128x128]^T, K=128
__device__ __forceinline__ void gemm1(float (&acc)[64], uint32_t aB, uint32_t bB,
                                      int m_base, int n_base, int lane) {
    #pragma unroll
    for (int i = 0; i < 64; i++) acc[i] = 0.0f;
    const int a_row = lane & 15, a_kc = lane >> 4;
    const int b_row = ((lane >> 4) << 3) + (lane & 7), b_kc = (lane >> 3) & 1;
    #pragma unroll
    for (int ks = 0; ks < 8; ks++) {
        uint32_t aH[2][4];
        #pragma unroll
        for (int t = 0; t < 2; t++) {
            int row = m_base + t * 16 + a_row;
            uint32_t off = (row << 8) + ((((ks << 1) + a_kc) ^ (row & 7)) << 4);
            ldsm4(aH[t], aB + off);
        }
        #pragma unroll
        for (int p = 0; p < 4; p++) {
            int row = n_base + p * 16 + b_row;
            uint32_t off = (row << 8) + ((((ks << 1) + b_kc) ^ (row & 7)) << 4);
            uint32_t bH[4];
            ldsm4(bH, bB + off);
            #pragma unroll
            for (int t = 0; t < 2; t++)
                #pragma unroll
                for (int s = 0; s < 2; s++)
                    mma16816h(&acc[(t * 8 + p * 2 + s) * 4], aH[t], &bH[2 * s]);
        }
    }
}

// GEMM2: C[32x64 tile] of adjI[64x64] @ z[64x128]; A stride 128B, B via ldsm.trans
__device__ __forceinline__ void gemm2(float (&acc)[64], uint32_t aB, uint32_t zB,
                                      int m_base, int n_base, int lane) {
    #pragma unroll
    for (int i = 0; i < 64; i++) acc[i] = 0.0f;
    const int a_row = lane & 15, a_kc = lane >> 4;
    const int grp = lane >> 3, r = lane & 7;
    #pragma unroll
    for (int ks = 0; ks < 4; ks++) {
        uint32_t aH[2][4];
        #pragma unroll
        for (int t = 0; t < 2; t++) {
            int row = m_base + t * 16 + a_row;
            uint32_t off = (row << 7) + ((((ks << 1) + a_kc) ^ (row & 7)) << 4);
            ldsm4(aH[t], aB + off);
        }
        int row_b = (ks << 4) + ((grp & 1) << 3) + r;
        #pragma unroll
        for (int p = 0; p < 4; p++) {
            int cc = ((n_base + p * 16) >> 3) + (grp >> 1);
            uint32_t off = (row_b << 8) + ((cc ^ (row_b & 7)) << 4);
            uint32_t bH[4];
            ldsm4t(bH, zB + off);
            #pragma unroll
            for (int t = 0; t < 2; t++)
                #pragma unroll
                for (int s = 0; s < 2; s++)
                    mma16816h(&acc[(t * 8 + p * 2 + s) * 4], aH[t], &bH[2 * s]);
        }
    }
}

// ---------------- fused prologue (unchanged / passing) ----------------
__global__ __launch_bounds__(256)
void prep_all(const float* __restrict__ emb, const float* __restrict__ W,
              const float* __restrict__ bias) {
    const int tid = threadIdx.x;
    if (blockIdx.x >= 128) {
        int idx = (int)(blockIdx.x - 128) * 256 + tid;
        int row = idx >> 7, col = idx & 127;
        float v = W[2 * 16384 + idx];
        int pos = row * 128 + (((col >> 3) ^ (row & 7)) << 3) + (col & 7);
        g_w3[pos] = __half_as_ushort(__float2half_rn(v));
        return;
    }
    extern __shared__ float fsm[];
    float* sW = fsm + FP_SW;
    float* sX = fsm + FP_SX;
    float* sZ = fsm + FP_SZ;
    float* sB = fsm + FP_SB;
    const int tx = tid & 31, ty = tid >> 5;
    const int r0 = (int)blockIdx.x * 16;

    const float4* W4 = reinterpret_cast<const float4*>(W);
    #pragma unroll
    for (int i = 0; i < 16; i++) {
        int q = tid + (i << 8);
        int k = q >> 5, c4 = (q & 31) << 2;
        *reinterpret_cast<float4*>(&sW[k * 132 + c4]) = __ldg(W4 + q);
    }
    const float4* E4 = reinterpret_cast<const float4*>(emb);
    #pragma unroll
    for (int i = 0; i < 2; i++) {
        int q = tid + (i << 8);
        int r = q >> 5, c4 = (q & 31) << 2;
        *reinterpret_cast<float4*>(&sX[r * 132 + c4]) =
            __ldg(E4 + (size_t)(r0 + r) * 32 + (q & 31));
    }
    if (tid < 128) sB[tid] = bias[tid];
    __syncthreads();

    float acc[2][4];
    #pragma unroll
    for (int i = 0; i < 2; i++)
        #pragma unroll
        for (int j = 0; j < 4; j++) acc[i][j] = 0.0f;
    for (int d4 = 0; d4 < 32; d4++) {
        float4 wv[4], ev[2];
        #pragma unroll
        for (int j = 0; j < 4; j++)
            wv[j] = *reinterpret_cast<const float4*>(&sW[(tx + 32 * j) * 132 + (d4 << 2)]);
        #pragma unroll
        for (int i = 0; i < 2; i++)
            ev[i] = *reinterpret_cast<const float4*>(&sX[(ty * 2 + i) * 132 + (d4 << 2)]);
        #pragma unroll
        for (int i = 0; i < 2; i++)
            #pragma unroll
            for (int j = 0; j < 4; j++) {
                acc[i][j] = fmaf(ev[i].x, wv[j].x, acc[i][j]);
                acc[i][j] = fmaf(ev[i].y, wv[j].y, acc[i][j]);
                acc[i][j] = fmaf(ev[i].z, wv[j].z, acc[i][j]);
                acc[i][j] = fmaf(ev[i].w, wv[j].w, acc[i][j]);
            }
    }
    #pragma unroll
    for (int i = 0; i < 2; i++)
        #pragma unroll
        for (int j = 0; j < 4; j++) {
            int k = tx + 32 * j;
            sZ[(ty * 2 + i) * 132 + k] = fmaxf(acc[i][j] + sB[k], 0.0f);
        }
    __syncthreads();

    #pragma unroll
    for (int i = 0; i < 16; i++) {
        int q = tid + (i << 8);
        int k = q >> 5, c4 = (q & 31) << 2;
        *reinterpret_cast<float4*>(&sW[k * 132 + c4]) = __ldg(W4 + 4096 + q);
    }
    __syncthreads();

    #pragma unroll
    for (int i = 0; i < 2; i++)
        #pragma unroll
        for (int j = 0; j < 4; j++) acc[i][j] = 0.0f;
    for (int d4 = 0; d4 < 32; d4++) {
        float4 wv[4], ev[2];
        #pragma unroll
        for (int j = 0; j < 4; j++)
            wv[j] = *reinterpret_cast<const float4*>(&sW[(tx + 32 * j) * 132 + (d4 << 2)]);
        #pragma unroll
        for (int i = 0; i < 2; i++)
            ev[i] = *reinterpret_cast<const float4*>(&sZ[(ty * 2 + i) * 132 + (d4 << 2)]);
        #pragma unroll
        for (int i = 0; i < 2; i++)
            #pragma unroll
            for (int j = 0; j < 4; j++) {
                acc[i][j] = fmaf(ev[i].x, wv[j].x, acc[i][j]);
                acc[i][j] = fmaf(ev[i].y, wv[j].y, acc[i][j]);
                acc[i][j] = fmaf(ev[i].z, wv[j].z, acc[i][j]);
                acc[i][j] = fmaf(ev[i].w, wv[j].w, acc[i][j]);
            }
    }
    #pragma unroll
    for (int i = 0; i < 2; i++)
        #pragma unroll
        for (int j = 0; j < 4; j++) {
            int r = r0 + ty * 2 + i;
            int k = tx + 32 * j;
            g_y1[r * 128 + k] = __half_as_ushort(__float2half_rn(acc[i][j]));
        }
}

// ---------------- main kernel: 2 graphs / CTA, 32x64 warp tiles ----------------
__global__ __launch_bounds__(256, 2)
void mpnn_main(const int* __restrict__ fps,
               const float* __restrict__ adj,
               const float* __restrict__ bias,
               float* __restrict__ out)
{
    extern __shared__ char smem[];
    const uint32_t sb = smem_u32(smem);
    const int tid = threadIdx.x, wid = tid >> 5, lane = tid & 31;
    const int bid = blockIdx.x;
    const int gw = wid >> 2;               // graph within CTA (0/1)
    const int wl = wid & 3;
    const int m_base = (wl & 1) << 5;      // 0 / 32
    const int n_base = (wl >> 1) << 6;     // 0 / 64

    const uint32_t ahg  = sb + SM_AH + gw * 16384;   // shared-space addr (asm only)
    const uint32_t adjg = sb + SM_ADJ + gw * 8192;   // shared-space addr (asm only)
    char* ahp = smem + SM_AH + gw * 16384;           // generic ptr (C++ stores)

    // ---- issue Y1 gather for BOTH graphs into WZ ----
    #pragma unroll
    for (int i = 0; i < 8; i++) {
        int idx = tid + (i << 8);                  // 0..2047: 128 rows x 16 chunks
        int m128 = idx >> 4, c = idx & 15;
        int mloc = m128 & 63;
        int fp = fps[bid * 128 + m128];
        const unsigned short* src = g_y1 + (size_t)fp * 128 + c * 8;
        cp16(sb + SM_WZ + (m128 >> 6) * 16384 + (mloc << 8) + ((c ^ (mloc & 7)) << 4), src);
    }
    CP_COMMIT();

    // ---- adjI = I + adj for both graphs: f16 + swizzle + colsum partials ----
    float4 sA = make_float4(0.f, 0.f, 0.f, 0.f);   // graph 0 partial (i<4)
    float4 sB4 = make_float4(0.f, 0.f, 0.f, 0.f);  // graph 1 partial (i>=4)
    {
        const float4* ag = reinterpret_cast<const float4*>(adj) + (size_t)bid * 2048;
        #pragma unroll
        for (int i = 0; i < 8; i++) {
            int q   = tid + (i << 8);              // 0..2047
            int gg  = q >> 10;
            int rem = q & 1023;
            int row = rem >> 4;
            int c4  = (rem & 15) << 2;
            float4 v = ag[q];
            float a0 = v.x + ((row == c4 + 0) ? 1.0f : 0.0f);
            float a1 = v.y + ((row == c4 + 1) ? 1.0f : 0.0f);
            float a2 = v.z + ((row == c4 + 2) ? 1.0f : 0.0f);
            float a3 = v.w + ((row == c4 + 3) ? 1.0f : 0.0f);
            if (i < 4) { sA.x += a0; sA.y += a1; sA.z += a2; sA.w += a3; }
            else       { sB4.x += a0; sB4.y += a1; sB4.z += a2; sB4.w += a3; }
            int off = (row << 7) + ((((c4 >> 3) ^ (row & 7)) << 4) | ((c4 & 7) << 1));
            *reinterpret_cast<uint32_t*>(smem + SM_ADJ + gg * 8192 + off)     = f16pack(a0, a1);
            *reinterpret_cast<uint32_t*>(smem + SM_ADJ + gg * 8192 + off + 4) = f16pack(a2, a3);
        }
    }
    {   // colsum partials in AH scratch (dead until z2 epi)
        float4* p0 = reinterpret_cast<float4*>(smem + SM_AH);
        float4* p1 = reinterpret_cast<float4*>(smem + SM_AH + 4096);
        p0[tid] = sA;
        p1[tid] = sB4;
    }
    __syncthreads();
    if (tid < 32) {
        int gg = tid >> 4, t16 = tid & 15;
        float4* part = reinterpret_cast<float4*>(smem + SM_AH + gg * 4096);
        float4 cs = part[t16];
        #pragma unroll
        for (int j = 1; j < 16; j++) {
            float4 p = part[t16 + 16 * j];
            cs.x += p.x; cs.y += p.y; cs.z += p.z; cs.w += p.w;
        }
        *reinterpret_cast<float4*>(smem + SM_AH + 8192 + gg * 256 + t16 * 16) = cs;
    }
    CP_WAIT0();            // Y1 (both graphs) arrived
    __syncthreads();

    // pooling weights for this warp's graph
    float wreg[4];
    {
        const float* wsm = reinterpret_cast<const float*>(smem + SM_AH + 8192 + gw * 256);
        int mb = m_base + (lane >> 2);
        #pragma unroll
        for (int q = 0; q < 4; q++) wreg[q] = wsm[mb + 8 * q];
    }

    float acc[64];

    // ================= stage A: D = adjI @ Y1g =================
    gemm2(acc, adjg, sb + SM_WZ + gw * 16384, m_base, n_base, lane);
    __syncthreads();       // Y1 consumed (both graphs), wreg reads done

    // stage W3 (full 32KB) into WZ; hides under z2-epi + stage B
    #pragma unroll
    for (int i = 0; i < 8; i++) {
        int idx = tid + (i << 8);                  // 0..2047
        cp16(sb + SM_WZ + idx * 16, g_w3 + idx * 8);
    }
    CP_COMMIT();

    // ---- epi: z2 = relu(D + b2) -> AH(graph) [generic-ptr stores] ----
    #pragma unroll
    for (int t = 0; t < 2; t++)
        #pragma unroll
        for (int nt = 0; nt < 8; nt++) {
            float* c = &acc[(t * 8 + nt) * 4];
            int k0 = n_base + nt * 8 + (lane & 3) * 2;
            int m  = m_base + t * 16 + (lane >> 2);
            float b0 = __ldg(bias + 128 + k0);
            float b1 = __ldg(bias + 128 + k0 + 1);
            *reinterpret_cast<uint32_t*>(ahp + swz256(m, k0)) =
                f16pack(fmaxf(c[0] + b0, 0.0f), fmaxf(c[1] + b1, 0.0f));
            *reinterpret_cast<uint32_t*>(ahp + swz256(m + 8, k0)) =
                f16pack(fmaxf(c[2] + b0, 0.0f), fmaxf(c[3] + b1, 0.0f));
        }
    __syncthreads();       // z2 visible

    // ================= stage B: h3 = adjI @ z2 =================
    gemm2(acc, adjg, ahg, m_base, n_base, lane);
    __syncthreads();       // z2 fully consumed

    // ---- epi: h3 -> AH(graph) (overwrite z2) [generic-ptr stores] ----
    #pragma unroll
    for (int t = 0; t < 2; t++)
        #pragma unroll
        for (int nt = 0; nt < 8; nt++) {
            float* c = &acc[(t * 8 + nt) * 4];
            int d0 = n_base + nt * 8 + (lane & 3) * 2;
            int m  = m_base + t * 16 + (lane >> 2);
            *reinterpret_cast<uint32_t*>(ahp + swz256(m, d0))     = f16pack(c[0], c[1]);
            *reinterpret_cast<uint32_t*>(ahp + swz256(m + 8, d0)) = f16pack(c[2], c[3]);
        }
    CP_WAIT0();            // W3 arrived (hidden under stage B)
    __syncthreads();

    // ================= stage C: D3 = h3 @ W3^T =================
    gemm1(acc, ahg, sb + SM_WZ, m_base, n_base, lane);
    __syncthreads();

    // ---- fused pooled epilogue: out[k] = sum_m w_m * relu(D3[m,k]+b3[k]) ----
    {
        float s[16];
        #pragma unroll
        for (int j = 0; j < 16; j++) s[j] = 0.0f;
        #pragma unroll
        for (int t = 0; t < 2; t++)
            #pragma unroll
            for (int nt = 0; nt < 8; nt++) {
                float* c = &acc[(t * 8 + nt) * 4];
                int k0 = n_base + nt * 8 + (lane & 3) * 2;
                float b0 = __ldg(bias + 256 + k0);
                float b1 = __ldg(bias + 256 + k0 + 1);
                #pragma unroll
                for (int r = 0; r < 4; r++) {
                    float v = fmaxf(c[r] + ((r & 1) ? b1 : b0), 0.0f);
                    s[nt * 2 + (r & 1)] += wreg[t * 2 + (r >> 1)] * v;
                }
            }
        #pragma unroll
        for (int off = 4; off < 32; off <<= 1)
            #pragma unroll
            for (int j = 0; j < 16; j++)
                s[j] += __shfl_xor_sync(0xffffffffu, s[j], off);

        float* pool = reinterpret_cast<float*>(smem + SM_POOL) + gw * 128;
        if ((wl & 1) == 0 && (lane >> 2) == 0) {
            #pragma unroll
            for (int nt = 0; nt < 8; nt++) {
                int k = n_base + nt * 8 + (lane & 3) * 2;
                *reinterpret_cast<float2*>(pool + k) = make_float2(s[nt * 2], s[nt * 2 + 1]);
            }
        }
        __syncthreads();
        if ((wl & 1) == 1 && (lane >> 2) == 0) {
            #pragma unroll
            for (int nt = 0; nt < 8; nt++) {
                int k = n_base + nt * 8 + (lane & 3) * 2;
                float2 p = *reinterpret_cast<float2*>(pool + k);
                *reinterpret_cast<float2*>(out + ((size_t)bid * 2 + gw) * 128 + k) =
                    make_float2(p.x + s[nt * 2], p.y + s[nt * 2 + 1]);
            }
        }
    }
}

extern "C" void kernel_launch(void* const* d_in, const int* in_sizes, int n_in,
                              void* d_out, int out_size)
{
    (void)in_sizes; (void)n_in; (void)out_size;
    const int*   fps = (const int*)  d_in[0];
    const float* adj = (const float*)d_in[1];
    const float* emb = (const float*)d_in[2];
    const float* W   = (const float*)d_in[3];
    const float* b   = (const float*)d_in[4];
    float*       out = (float*)d_out;

    cudaFuncSetAttribute(prep_all, cudaFuncAttributeMaxDynamicSharedMemorySize, FP_TOT);
    prep_all<<<192, 256, FP_TOT>>>(emb, W, b);

    cudaFuncSetAttribute(mpnn_main, cudaFuncAttributeMaxDynamicSharedMemorySize, SM_TOTAL);
    mpnn_main<<<2048, 256, SM_TOTAL>>>(fps, adj, b, out);
}